// round 13
// baseline (speedup 1.0000x reference)
#include <cuda_runtime.h>
#include <cuda_bf16.h>
#include <mma.h>
#include <math.h>
#include <math_constants.h>
#include <stdint.h>

using namespace nvcuda;

typedef unsigned long long ull;

// Problem constants
#define HH    16
#define DD    64
#define HIDN  1024
#define NROWS 65536         // B*L*H
#define NBL   4096          // B*L
#define NOUT  128           // 2*D

// __device__ scratch (allocation-free rule)
__device__ float g_hidp[4][NBL * NOUT];      // K-split partials of hidden@W1[:1024] (+b1 in part 0)
__device__ float g_wstat[12 * NOUT];         // fp32 column sums of W1 stat-block rows
__device__ __nv_bfloat16 g_Bhi[4][8192];     // branch-tail W1^T per chunk [n*64+k], hi part
__device__ __nv_bfloat16 g_Blo[4][8192];     // lo part

// ---------------------------------------------------------------------------
// helpers
// ---------------------------------------------------------------------------
__device__ __forceinline__ ull fma2(ull a, ull b, ull c) {
    ull d; asm("fma.rn.f32x2 %0, %1, %2, %3;" : "=l"(d) : "l"(a), "l"(b), "l"(c));
    return d;
}
__device__ __forceinline__ ull dup2(float x) {
    ull d; asm("mov.b64 %0, {%1, %1};" : "=l"(d) : "f"(x));
    return d;
}
__device__ __forceinline__ uint32_t cvt_bf16x2(float hi_elem, float lo_elem) {
    uint32_t r;
    asm("cvt.rn.bf16x2.f32 %0, %1, %2;" : "=r"(r) : "f"(hi_elem), "f"(lo_elem));
    return r;
}
__device__ __forceinline__ void cp16(void* dst_smem, const void* src) {
    uint32_t d = (uint32_t)__cvta_generic_to_shared(dst_smem);
    asm volatile("cp.async.cg.shared.global [%0], [%1], 16;" :: "r"(d), "l"(src) : "memory");
}
#define CP_COMMIT() asm volatile("cp.async.commit_group;" ::: "memory")
#define CP_WAIT0()  asm volatile("cp.async.wait_group 0;" ::: "memory")

// Named barriers (512 participants each). FULL: producers arrive, consumers
// sync. EMPTY: consumers arrive, producers sync.
#define BAR_SYNC(id)   asm volatile("bar.sync %0, 512;"   :: "r"(id) : "memory")
#define BAR_ARRIVE(id) asm volatile("bar.arrive %0, 512;" :: "r"(id) : "memory")
#define NB_FULL0  1
#define NB_FULL1  2
#define NB_EMPTY0 3
#define NB_EMPTY1 4

// ---------------------------------------------------------------------------
// hid + prep fused kernel (EXACT R9 winner).
// Blocks 0..255: FFMA2 hidden partial GEMM (rowgroup rg=bid>>2, K-split ks=bid&3)
// Blocks 256..271: branch-tail weight prep; Blocks 272..283: wstat
// ---------------------------------------------------------------------------
#define HID_SMEM_BYTES (12544 * 4)

__global__ __launch_bounds__(256)
void hid_kernel(const float* __restrict__ hidden,
                const float* __restrict__ W1,
                const float* __restrict__ b1) {
    if (blockIdx.x >= 256) {
        const int bid = blockIdx.x;
        if (bid < 272) {
            const int c = (bid - 256) >> 2, q = bid & 3;
            const int rowbase = 1792 + c * 64;
            const int e0 = q * 2048;
            for (int e = e0 + threadIdx.x; e < e0 + 2048; e += 256) {
                const int k = e >> 7, n = e & 127;
                const float x = W1[(size_t)(rowbase + k) * NOUT + n];
                const __nv_bfloat16 hi = __float2bfloat16(x);
                const __nv_bfloat16 lo = __float2bfloat16(x - __bfloat162float(hi));
                g_Bhi[c][n * 64 + k] = hi;
                g_Blo[c][n * 64 + k] = lo;
            }
        } else {
            const int j = bid - 272;
            const int o = threadIdx.x & 127;
            const int half = threadIdx.x >> 7;
            __shared__ float part[256];
            const float* base = W1 + (size_t)(HIDN + j * 64 + half * 32) * NOUT + o;
            float s = 0.f;
#pragma unroll
            for (int d = 0; d < 32; ++d) s += base[(size_t)d * NOUT];
            part[threadIdx.x] = s;
            __syncthreads();
            if (half == 0) g_wstat[j * NOUT + o] = part[o] + part[128 + o];
        }
        return;
    }

    extern __shared__ float sm[];
    float* Bs  = sm;           // [64][128]
    float* AsT = sm + 8192;    // [64][68]

    const int tid = threadIdx.x;
    const int rg  = blockIdx.x >> 2;
    const int ks  = blockIdx.x & 3;
    const int m0  = rg * 64;
    const int k0b = ks * 256;
    const int tx  = tid & 15, ty = tid >> 4;
    const int tx4 = tx * 4,  ty4 = ty * 4;

    ull acc[4][4] = {};

    for (int t = 0; t < 4; ++t) {
        const int k0 = k0b + t * 64;
        {
            int idx = tid;
#pragma unroll
            for (int i = 0; i < 16; ++i, idx += 256) {
                int r = idx >> 6, kk = idx & 63;
                AsT[kk * 68 + r] = hidden[(size_t)(m0 + r) * HIDN + k0 + kk];
            }
        }
        {
            int i4 = tid;
#pragma unroll
            for (int i = 0; i < 8; ++i, i4 += 256) {
                int kk = i4 >> 5, c4 = (i4 & 31) * 4;
                *reinterpret_cast<float4*>(&Bs[kk * 128 + c4]) =
                    *reinterpret_cast<const float4*>(&W1[(size_t)(k0 + kk) * NOUT + c4]);
            }
        }
        __syncthreads();

#pragma unroll 8
        for (int kk = 0; kk < 64; ++kk) {
            const float4 a4 = *reinterpret_cast<const float4*>(&AsT[kk * 68 + ty4]);
            const ulonglong2 bv0 = *reinterpret_cast<const ulonglong2*>(&Bs[kk * 128 + tx4]);
            const ulonglong2 bv1 = *reinterpret_cast<const ulonglong2*>(&Bs[kk * 128 + 64 + tx4]);
            ull ad[4] = {dup2(a4.x), dup2(a4.y), dup2(a4.z), dup2(a4.w)};
            ull bq[4] = {bv0.x, bv0.y, bv1.x, bv1.y};
#pragma unroll
            for (int i = 0; i < 4; ++i)
#pragma unroll
                for (int jj = 0; jj < 4; ++jj)
                    acc[i][jj] = fma2(ad[i], bq[jj], acc[i][jj]);
        }
        __syncthreads();
    }

    float* outp = g_hidp[ks];
    float4 bb0 = {0, 0, 0, 0}, bb1 = {0, 0, 0, 0};
    if (ks == 0) {
        bb0 = *reinterpret_cast<const float4*>(&b1[tx4]);
        bb1 = *reinterpret_cast<const float4*>(&b1[64 + tx4]);
    }
#pragma unroll
    for (int rr = 0; rr < 4; ++rr) {
        const int r = ty4 + rr;
        float2 p0 = *reinterpret_cast<float2*>(&acc[rr][0]);
        float2 p1 = *reinterpret_cast<float2*>(&acc[rr][1]);
        float2 p2 = *reinterpret_cast<float2*>(&acc[rr][2]);
        float2 p3 = *reinterpret_cast<float2*>(&acc[rr][3]);
        float4 v0 = {p0.x + bb0.x, p0.y + bb0.y, p1.x + bb0.z, p1.y + bb0.w};
        float4 v1 = {p2.x + bb1.x, p2.y + bb1.y, p3.x + bb1.z, p3.y + bb1.w};
        *reinterpret_cast<float4*>(&outp[(size_t)(m0 + r) * NOUT + tx4]) = v0;
        *reinterpret_cast<float4*>(&outp[(size_t)(m0 + r) * NOUT + 64 + tx4]) = v1;
    }
}

// ---------------------------------------------------------------------------
// main: warp-specialized wmma bf16 hi/lo GEMM.
// 512 threads, 1 CTA/SM. Warps 0-7 consumers (HMMA, 4(M)x2(N), 32x64 tiles);
// warps 8-15 producers (A convert + stats + cp.async B). Double-buffered
// A/B smem; FULL/EMPTY named-barrier handshake.
//
// smem (bytes):
//   buf b (b=0,1) at b*73728: AH(18432) AL(18432) BH(18432) BL(18432)
//   Ds[128][136] f32 overlays buffer 0 in epilogue (69632 <= 73728)
//   WST 147456 | SST 153600 | W2 159744 | HIDC 161792 | SLOG 165888(128x16)
//   total 174080
// ---------------------------------------------------------------------------
#define BUF_SZ   73728
#define OFF_AHb(b) ((b) * BUF_SZ)
#define OFF_ALb(b) ((b) * BUF_SZ + 18432)
#define OFF_BHb(b) ((b) * BUF_SZ + 36864)
#define OFF_BLb(b) ((b) * BUF_SZ + 55296)
#define OFF_WST  147456
#define OFF_SST  153600
#define OFF_W2   159744
#define OFF_HIDC 161792
#define OFF_SLOG 165888
#define MAIN_SMEM_BYTES 174080

#define ALD 72     // A/B smem leading dim (bf16 elements)
#define DLD 136    // D smem leading dim (floats)

__global__ __launch_bounds__(512, 1)
void main_wmma_kernel(const float* __restrict__ br0, const float* __restrict__ br1,
                      const float* __restrict__ br2, const float* __restrict__ br3,
                      const float* __restrict__ W2,  const float* __restrict__ b2,
                      const float* __restrict__ eps_floor,
                      const float* __restrict__ temp, float* __restrict__ out) {
    extern __shared__ char smc[];
    float* Ds    = reinterpret_cast<float*>(smc);             // epilogue overlay (buf 0)
    float* sWst  = reinterpret_cast<float*>(smc + OFF_WST);
    float* sStat = reinterpret_cast<float*>(smc + OFF_SST);
    float* sW2   = reinterpret_cast<float*>(smc + OFF_W2);
    float* hidc  = reinterpret_cast<float*>(smc + OFF_HIDC);
    float* sLog  = reinterpret_cast<float*>(smc + OFF_SLOG);

    const int tid = threadIdx.x;
    const int wid = tid >> 5;
    const int m0  = blockIdx.x * 128;

    // Prologue one-time loads (all 512 threads; consumed after __syncthreads)
    for (int i = tid; i < 512; i += 512) sW2[i] = W2[i];
    for (int i = tid; i < 12 * NOUT; i += 512) sWst[i] = g_wstat[i];
    for (int i = tid; i < 1024; i += 512) {
        const size_t g = (size_t)(blockIdx.x * 8) * NOUT + i;
        hidc[i] = (g_hidp[0][g] + g_hidp[1][g]) + (g_hidp[2][g] + g_hidp[3][g]);
    }

    if (tid < 256) {
        // ================= consumers: HMMA =================
        const int wm = wid & 3, wn = wid >> 2;
        wmma::fragment<wmma::accumulator, 16, 16, 16, float> acc[2][4];
#pragma unroll
        for (int i = 0; i < 2; ++i)
#pragma unroll
            for (int j = 0; j < 4; ++j) wmma::fill_fragment(acc[i][j], 0.0f);

#pragma unroll 1
        for (int p = 0; p < 4; ++p) {
            const int b = p & 1;
            BAR_SYNC(NB_FULL0 + b);
            const __nv_bfloat16* AH = reinterpret_cast<const __nv_bfloat16*>(smc + OFF_AHb(b));
            const __nv_bfloat16* AL = reinterpret_cast<const __nv_bfloat16*>(smc + OFF_ALb(b));
            const __nv_bfloat16* BH = reinterpret_cast<const __nv_bfloat16*>(smc + OFF_BHb(b));
            const __nv_bfloat16* BL = reinterpret_cast<const __nv_bfloat16*>(smc + OFF_BLb(b));
#pragma unroll
            for (int kk = 0; kk < 4; ++kk) {
                wmma::fragment<wmma::matrix_a, 16, 16, 16, __nv_bfloat16, wmma::row_major> ahi[2], alo[2];
#pragma unroll
                for (int i = 0; i < 2; ++i) {
                    const int ro = (wm * 32 + i * 16) * ALD + kk * 16;
                    wmma::load_matrix_sync(ahi[i], AH + ro, ALD);
                    wmma::load_matrix_sync(alo[i], AL + ro, ALD);
                }
#pragma unroll
                for (int j = 0; j < 4; ++j) {
                    wmma::fragment<wmma::matrix_b, 16, 16, 16, __nv_bfloat16, wmma::col_major> bhi, blo;
                    const int bo = (wn * 64 + j * 16) * ALD + kk * 16;
                    wmma::load_matrix_sync(bhi, BH + bo, ALD);
                    wmma::load_matrix_sync(blo, BL + bo, ALD);
#pragma unroll
                    for (int i = 0; i < 2; ++i) {
                        wmma::mma_sync(acc[i][j], ahi[i], bhi, acc[i][j]);
                        wmma::mma_sync(acc[i][j], alo[i], bhi, acc[i][j]);
                        wmma::mma_sync(acc[i][j], ahi[i], blo, acc[i][j]);
                    }
                }
            }
            if (p < 2) BAR_ARRIVE(NB_EMPTY0 + b);   // buffer b free for refill
        }

        __syncthreads();   // all consumers done with all buffers
        // store D into overlay (buffer-0 region)
#pragma unroll
        for (int i = 0; i < 2; ++i)
#pragma unroll
            for (int j = 0; j < 4; ++j)
                wmma::store_matrix_sync(Ds + (wm * 32 + i * 16) * DLD + wn * 64 + j * 16,
                                        acc[i][j], DLD, wmma::mem_row_major);
    } else {
        // ================= producers: stage A/B + stats =================
        const int ptid  = tid - 256;
        const int arow  = ptid >> 1;
        const int ahalf = ptid & 1;
        const int kbase = ahalf * 32;

#pragma unroll 1
        for (int p = 0; p < 4; ++p) {
            const int b = p & 1;
            if (p >= 2) BAR_SYNC(NB_EMPTY0 + b);    // wait consumers done with buf b

            __nv_bfloat16* AH = reinterpret_cast<__nv_bfloat16*>(smc + OFF_AHb(b));
            __nv_bfloat16* AL = reinterpret_cast<__nv_bfloat16*>(smc + OFF_ALb(b));
            __nv_bfloat16* BH = reinterpret_cast<__nv_bfloat16*>(smc + OFF_BHb(b));
            __nv_bfloat16* BL = reinterpret_cast<__nv_bfloat16*>(smc + OFF_BLb(b));

            // async B copies first (overlap with A convert)
            {
                const int n = ptid >> 1;
                const int kb = ahalf * 32;
#pragma unroll
                for (int q = 0; q < 4; ++q) {
                    cp16(&BH[n * ALD + kb + q * 8], &g_Bhi[p][n * 64 + kb + q * 8]);
                    cp16(&BL[n * ALD + kb + q * 8], &g_Blo[p][n * 64 + kb + q * 8]);
                }
                CP_COMMIT();
            }

            // stage A + stats
            {
                const float* brp = (p == 0) ? br0 : (p == 1) ? br1 : (p == 2) ? br2 : br3;
                const float* src = brp + (size_t)(m0 + arow) * DD + kbase;
                float s = 0.f, sq = 0.f, mx = -CUDART_INF_F;
#pragma unroll
                for (int j = 0; j < 8; ++j) {
                    const float4 v = *reinterpret_cast<const float4*>(src + j * 4);
                    s += (v.x + v.y) + (v.z + v.w);
                    sq = fmaf(v.x, v.x, sq); sq = fmaf(v.y, v.y, sq);
                    sq = fmaf(v.z, v.z, sq); sq = fmaf(v.w, v.w, sq);
                    mx = fmaxf(mx, fmaxf(fmaxf(v.x, v.y), fmaxf(v.z, v.w)));
                    const uint32_t h0 = cvt_bf16x2(v.y, v.x);
                    const uint32_t h1 = cvt_bf16x2(v.w, v.z);
                    const float r0 = v.x - __uint_as_float(h0 << 16);
                    const float r1 = v.y - __uint_as_float(h0 & 0xffff0000u);
                    const float r2 = v.z - __uint_as_float(h1 << 16);
                    const float r3 = v.w - __uint_as_float(h1 & 0xffff0000u);
                    const uint32_t l0 = cvt_bf16x2(r1, r0);
                    const uint32_t l1 = cvt_bf16x2(r3, r2);
                    const int eoff = arow * ALD + kbase + j * 4;
                    uint2 hv = {h0, h1}, lv = {l0, l1};
                    *reinterpret_cast<uint2*>(&AH[eoff]) = hv;
                    *reinterpret_cast<uint2*>(&AL[eoff]) = lv;
                }
                s  += __shfl_xor_sync(0xffffffffu, s, 1);
                sq += __shfl_xor_sync(0xffffffffu, sq, 1);
                mx  = fmaxf(mx, __shfl_xor_sync(0xffffffffu, mx, 1));
                if (ahalf == 0) {
                    sStat[arow * 12 + p * 3 + 0] = s * (1.f / 64.f);
                    sStat[arow * 12 + p * 3 + 1] = sqrtf(fmaxf(sq * (1.f / 64.f), 1e-8f));
                    sStat[arow * 12 + p * 3 + 2] = mx;
                }
            }

            CP_WAIT0();                  // B landed
            BAR_ARRIVE(NB_FULL0 + b);    // buffer b ready
        }
        __syncthreads();   // join consumers (pre-Ds-store sync)
    }

    __syncthreads();       // Ds stored; sStat complete; everyone aligned

    // ---- epilogue: hid + stats, gelu, @W2 partials (512 threads) ----
    {
        const int row = tid >> 2;
        const int q   = tid & 3;
        const int c0  = q * 32;
        const float* hrow = &hidc[(row >> 4) * 128];
        const float* drow = &Ds[row * DLD];
        float st[12];
#pragma unroll
        for (int j = 0; j < 12; ++j) st[j] = sStat[row * 12 + j];
        float lg0 = 0.f, lg1 = 0.f, lg2 = 0.f, lg3 = 0.f;
#pragma unroll 8
        for (int ci = 0; ci < 32; ++ci) {
            const int cc = c0 + ci;
            float a = drow[cc] + hrow[cc];
#pragma unroll
            for (int j = 0; j < 12; ++j) a = fmaf(st[j], sWst[j * NOUT + cc], a);
            a *= normcdff(a);                      // exact gelu
            const float4 w = *reinterpret_cast<const float4*>(&sW2[cc * 4]);
            lg0 = fmaf(a, w.x, lg0);
            lg1 = fmaf(a, w.y, lg1);
            lg2 = fmaf(a, w.z, lg2);
            lg3 = fmaf(a, w.w, lg3);
        }
        sLog[row * 16 + q * 4 + 0] = lg0;
        sLog[row * 16 + q * 4 + 1] = lg1;
        sLog[row * 16 + q * 4 + 2] = lg2;
        sLog[row * 16 + q * 4 + 3] = lg3;
    }
    __syncthreads();

    // ---- softmax / floor / renorm ----
    if (tid < 128) {
        const int m = m0 + tid;
        const int head = m & (HH - 1);
        const float* lrow = &sLog[tid * 16];
        float l0 = lrow[0] + lrow[4] + lrow[8]  + lrow[12] + b2[0];
        float l1 = lrow[1] + lrow[5] + lrow[9]  + lrow[13] + b2[1];
        float l2 = lrow[2] + lrow[6] + lrow[10] + lrow[14] + b2[2];
        float l3 = lrow[3] + lrow[7] + lrow[11] + lrow[15] + b2[3];
        const float t = fminf(fmaxf(temp[head], 0.2f), 10.f);
        const float inv_t = 1.f / t;
        const float mxl = fmaxf(fmaxf(l0, l1), fmaxf(l2, l3));
        const float e0 = expf((l0 - mxl) * inv_t);
        const float e1 = expf((l1 - mxl) * inv_t);
        const float e2 = expf((l2 - mxl) * inv_t);
        const float e3 = expf((l3 - mxl) * inv_t);
        const float inv = 1.f / (e0 + e1 + e2 + e3);
        float w0 = e0 * inv, w1 = e1 * inv, w2 = e2 * inv, w3 = e3 * inv;
        const float* ef = &eps_floor[head * 4];
        w0 = fmaxf(w0, fminf(fmaxf(ef[0], 1e-7f), 0.1f));
        w1 = fmaxf(w1, fminf(fmaxf(ef[1], 1e-7f), 0.1f));
        w2 = fmaxf(w2, fminf(fmaxf(ef[2], 1e-7f), 0.1f));
        w3 = fmaxf(w3, fminf(fmaxf(ef[3], 1e-7f), 0.1f));
        const float inv2 = 1.f / (w0 + w1 + w2 + w3);
        float4 o = {w0 * inv2, w1 * inv2, w2 * inv2, w3 * inv2};
        *reinterpret_cast<float4*>(&out[(size_t)m * 4]) = o;
    }
}

// ---------------------------------------------------------------------------
// Launch
// ---------------------------------------------------------------------------
extern "C" void kernel_launch(void* const* d_in, const int* in_sizes, int n_in,
                              void* d_out, int out_size) {
    const float* hidden = (const float*)d_in[0];
    const float* br0    = (const float*)d_in[1];
    const float* br1    = (const float*)d_in[2];
    const float* br2    = (const float*)d_in[3];
    const float* br3    = (const float*)d_in[4];
    const float* W1     = (const float*)d_in[5];
    const float* b1     = (const float*)d_in[6];
    const float* W2     = (const float*)d_in[7];
    const float* b2     = (const float*)d_in[8];
    const float* epsf   = (const float*)d_in[9];
    const float* temp   = (const float*)d_in[10];
    float* out = (float*)d_out;

    cudaFuncSetAttribute(hid_kernel, cudaFuncAttributeMaxDynamicSharedMemorySize,
                         HID_SMEM_BYTES);
    cudaFuncSetAttribute(main_wmma_kernel, cudaFuncAttributeMaxDynamicSharedMemorySize,
                         MAIN_SMEM_BYTES);

    hid_kernel<<<284, 256, HID_SMEM_BYTES>>>(hidden, W1, b1);
    main_wmma_kernel<<<NROWS / 128, 512, MAIN_SMEM_BYTES>>>(br0, br1, br2, br3,
                                                            W2, b2, epsf, temp, out);
}

// round 14
// speedup vs baseline: 2.0901x; 2.0901x over previous
#include <cuda_runtime.h>
#include <cuda_bf16.h>
#include <mma.h>
#include <math.h>
#include <math_constants.h>
#include <stdint.h>

using namespace nvcuda;

typedef unsigned long long ull;

// Problem constants
#define HH    16
#define DD    64
#define HIDN  1024
#define NROWS 65536         // B*L*H
#define NBL   4096          // B*L
#define NOUT  128           // 2*D

// __device__ scratch (allocation-free rule)
__device__ float g_hidp[4][NBL * NOUT];      // K-split partials of hidden@W1[:1024] (+b1 in part 0)
__device__ float g_wstat[12 * NOUT];         // fp32 column sums of W1 stat-block rows
__device__ float g_Btf[4][8192];             // branch-tail W1^T per chunk [n*64+k], fp32 (for TF32 MMA)

// ---------------------------------------------------------------------------
// helpers
// ---------------------------------------------------------------------------
__device__ __forceinline__ ull fma2(ull a, ull b, ull c) {
    ull d; asm("fma.rn.f32x2 %0, %1, %2, %3;" : "=l"(d) : "l"(a), "l"(b), "l"(c));
    return d;
}
__device__ __forceinline__ ull dup2(float x) {
    ull d; asm("mov.b64 %0, {%1, %1};" : "=l"(d) : "f"(x));
    return d;
}
__device__ __forceinline__ void cp16(void* dst_smem, const void* src) {
    uint32_t d = (uint32_t)__cvta_generic_to_shared(dst_smem);
    asm volatile("cp.async.cg.shared.global [%0], [%1], 16;" :: "r"(d), "l"(src) : "memory");
}
#define CP_COMMIT() asm volatile("cp.async.commit_group;" ::: "memory")
#define CP_WAIT0()  asm volatile("cp.async.wait_group 0;" ::: "memory")

// ---------------------------------------------------------------------------
// hid + prep fused kernel (R9 winner structure).
// Blocks 0..255: FFMA2 hidden partial GEMM (rowgroup rg=bid>>2, K-split ks=bid&3)
// Blocks 256..271: branch-tail weight transpose (fp32); Blocks 272..283: wstat
// ---------------------------------------------------------------------------
#define HID_SMEM_BYTES (12544 * 4)

__global__ __launch_bounds__(256)
void hid_kernel(const float* __restrict__ hidden,
                const float* __restrict__ W1,
                const float* __restrict__ b1) {
    if (blockIdx.x >= 256) {
        const int bid = blockIdx.x;
        if (bid < 272) {
            // branch-tail weight chunks: plain fp32 transpose
            const int c = (bid - 256) >> 2, q = bid & 3;
            const int rowbase = 1792 + c * 64;
            const int e0 = q * 2048;
            for (int e = e0 + threadIdx.x; e < e0 + 2048; e += 256) {
                const int k = e >> 7, n = e & 127;
                g_Btf[c][n * 64 + k] = W1[(size_t)(rowbase + k) * NOUT + n];
            }
        } else {
            // wstat
            const int j = bid - 272;
            const int o = threadIdx.x & 127;
            const int half = threadIdx.x >> 7;
            __shared__ float part[256];
            const float* base = W1 + (size_t)(HIDN + j * 64 + half * 32) * NOUT + o;
            float s = 0.f;
#pragma unroll
            for (int d = 0; d < 32; ++d) s += base[(size_t)d * NOUT];
            part[threadIdx.x] = s;
            __syncthreads();
            if (half == 0) g_wstat[j * NOUT + o] = part[o] + part[128 + o];
        }
        return;
    }

    extern __shared__ float sm[];
    float* Bs  = sm;           // [64][128]
    float* AsT = sm + 8192;    // [64][68]

    const int tid = threadIdx.x;
    const int rg  = blockIdx.x >> 2;
    const int ks  = blockIdx.x & 3;
    const int m0  = rg * 64;
    const int k0b = ks * 256;
    const int tx  = tid & 15, ty = tid >> 4;
    const int tx4 = tx * 4,  ty4 = ty * 4;

    ull acc[4][4] = {};

    for (int t = 0; t < 4; ++t) {
        const int k0 = k0b + t * 64;
        {
            int idx = tid;
#pragma unroll
            for (int i = 0; i < 16; ++i, idx += 256) {
                int r = idx >> 6, kk = idx & 63;
                AsT[kk * 68 + r] = hidden[(size_t)(m0 + r) * HIDN + k0 + kk];
            }
        }
        {
            int i4 = tid;
#pragma unroll
            for (int i = 0; i < 8; ++i, i4 += 256) {
                int kk = i4 >> 5, c4 = (i4 & 31) * 4;
                *reinterpret_cast<float4*>(&Bs[kk * 128 + c4]) =
                    *reinterpret_cast<const float4*>(&W1[(size_t)(k0 + kk) * NOUT + c4]);
            }
        }
        __syncthreads();

#pragma unroll 8
        for (int kk = 0; kk < 64; ++kk) {
            const float4 a4 = *reinterpret_cast<const float4*>(&AsT[kk * 68 + ty4]);
            const ulonglong2 bv0 = *reinterpret_cast<const ulonglong2*>(&Bs[kk * 128 + tx4]);
            const ulonglong2 bv1 = *reinterpret_cast<const ulonglong2*>(&Bs[kk * 128 + 64 + tx4]);
            ull ad[4] = {dup2(a4.x), dup2(a4.y), dup2(a4.z), dup2(a4.w)};
            ull bq[4] = {bv0.x, bv0.y, bv1.x, bv1.y};
#pragma unroll
            for (int i = 0; i < 4; ++i)
#pragma unroll
                for (int jj = 0; jj < 4; ++jj)
                    acc[i][jj] = fma2(ad[i], bq[jj], acc[i][jj]);
        }
        __syncthreads();
    }

    float* outp = g_hidp[ks];
    float4 bb0 = {0, 0, 0, 0}, bb1 = {0, 0, 0, 0};
    if (ks == 0) {
        bb0 = *reinterpret_cast<const float4*>(&b1[tx4]);
        bb1 = *reinterpret_cast<const float4*>(&b1[64 + tx4]);
    }
#pragma unroll
    for (int rr = 0; rr < 4; ++rr) {
        const int r = ty4 + rr;
        float2 p0 = *reinterpret_cast<float2*>(&acc[rr][0]);
        float2 p1 = *reinterpret_cast<float2*>(&acc[rr][1]);
        float2 p2 = *reinterpret_cast<float2*>(&acc[rr][2]);
        float2 p3 = *reinterpret_cast<float2*>(&acc[rr][3]);
        float4 v0 = {p0.x + bb0.x, p0.y + bb0.y, p1.x + bb0.z, p1.y + bb0.w};
        float4 v1 = {p2.x + bb1.x, p2.y + bb1.y, p3.x + bb1.z, p3.y + bb1.w};
        *reinterpret_cast<float4*>(&outp[(size_t)(m0 + r) * NOUT + tx4]) = v0;
        *reinterpret_cast<float4*>(&outp[(size_t)(m0 + r) * NOUT + 64 + tx4]) = v1;
    }
}

// ---------------------------------------------------------------------------
// main: TF32 wmma GEMM (single pass, m16n16k8), R9 shell.
// M-tile=128 rows, N=128, K=256 (4 branch chunks of 64).
// 8 warps: 4(M) x 2(N); warp tile 32x64 = 2x4 acc fragments.
// A staged as raw fp32 (no conversion); B via cp.async fp32.
//
// smem (bytes) — identical budget to R9:
//   AS 0      (128x72 f32 = 36864)   \ overlaid by Ds[128][136] f32
//   BS 36864  (128n x 72k f32)       /  (69632 <= 73728) in epilogue
//   WST 73728 | SST 79872 | W2 86016 | HIDC 88064 | SLOG 92160
//   total 96256 -> 2 CTAs/SM with __launch_bounds__(256,2)
// ---------------------------------------------------------------------------
#define OFF_AS   0
#define OFF_BS   36864
#define OFF_WST  73728
#define OFF_SST  79872
#define OFF_W2   86016
#define OFF_HIDC 88064
#define OFF_SLOG 92160
#define MAIN_SMEM_BYTES 96256

#define ALD 72     // A/B smem leading dim (fp32 elements)
#define DLD 136    // D smem leading dim (floats)

__global__ __launch_bounds__(256, 2)
void main_wmma_kernel(const float* __restrict__ br0, const float* __restrict__ br1,
                      const float* __restrict__ br2, const float* __restrict__ br3,
                      const float* __restrict__ W2,  const float* __restrict__ b2,
                      const float* __restrict__ eps_floor,
                      const float* __restrict__ temp, float* __restrict__ out) {
    extern __shared__ char smc[];
    float* AS    = reinterpret_cast<float*>(smc + OFF_AS);
    float* BS    = reinterpret_cast<float*>(smc + OFF_BS);
    float* Ds    = reinterpret_cast<float*>(smc);             // epilogue overlay
    float* sWst  = reinterpret_cast<float*>(smc + OFF_WST);
    float* sStat = reinterpret_cast<float*>(smc + OFF_SST);
    float* sW2   = reinterpret_cast<float*>(smc + OFF_W2);
    float* hidc  = reinterpret_cast<float*>(smc + OFF_HIDC);
    float* sLog  = reinterpret_cast<float*>(smc + OFF_SLOG);

    const int tid = threadIdx.x;
    const int wid = tid >> 5;
    const int m0  = blockIdx.x * 128;
    const int wm  = wid & 3, wn = wid >> 2;

    // Prologue one-time loads (covered by chunk-0 __syncthreads)
    for (int i = tid; i < 1024; i += 256) {
        const size_t g = (size_t)(blockIdx.x * 8) * NOUT + i;
        hidc[i] = (g_hidp[0][g] + g_hidp[1][g]) + (g_hidp[2][g] + g_hidp[3][g]);
    }
    for (int i = tid; i < 512; i += 256)       sW2[i]  = W2[i];
    for (int i = tid; i < 12 * NOUT; i += 256) sWst[i] = g_wstat[i];

    wmma::fragment<wmma::accumulator, 16, 16, 8, float> acc[2][4];
#pragma unroll
    for (int i = 0; i < 2; ++i)
#pragma unroll
        for (int j = 0; j < 4; ++j) wmma::fill_fragment(acc[i][j], 0.0f);

    const int arow  = tid >> 1;
    const int ahalf = tid & 1;
    const int kbase = ahalf * 32;

#pragma unroll 1
    for (int p = 0; p < 4; ++p) {
        const float* brp = (p == 0) ? br0 : (p == 1) ? br1 : (p == 2) ? br2 : br3;

        // ---- issue async B copies first (fp32, overlap with A stage) ----
        {
            const int n = tid >> 1;
            const int kb = ahalf * 32;
#pragma unroll
            for (int q = 0; q < 8; ++q)
                cp16(&BS[n * ALD + kb + q * 4], &g_Btf[p][n * 64 + kb + q * 4]);
            CP_COMMIT();
        }

        // ---- stage A (raw fp32) + stats ----
        {
            const float* src = brp + (size_t)(m0 + arow) * DD + kbase;
            float s = 0.f, sq = 0.f, mx = -CUDART_INF_F;
#pragma unroll
            for (int j = 0; j < 8; ++j) {
                const float4 v = *reinterpret_cast<const float4*>(src + j * 4);
                s += (v.x + v.y) + (v.z + v.w);
                sq = fmaf(v.x, v.x, sq); sq = fmaf(v.y, v.y, sq);
                sq = fmaf(v.z, v.z, sq); sq = fmaf(v.w, v.w, sq);
                mx = fmaxf(mx, fmaxf(fmaxf(v.x, v.y), fmaxf(v.z, v.w)));
                *reinterpret_cast<float4*>(&AS[arow * ALD + kbase + j * 4]) = v;
            }
            s  += __shfl_xor_sync(0xffffffffu, s, 1);
            sq += __shfl_xor_sync(0xffffffffu, sq, 1);
            mx  = fmaxf(mx, __shfl_xor_sync(0xffffffffu, mx, 1));
            if (ahalf == 0) {
                sStat[arow * 12 + p * 3 + 0] = s * (1.f / 64.f);
                sStat[arow * 12 + p * 3 + 1] = sqrtf(fmaxf(sq * (1.f / 64.f), 1e-8f));
                sStat[arow * 12 + p * 3 + 2] = mx;
            }
        }

        CP_WAIT0();
        __syncthreads();

        // ---- TF32 HMMA: K=64 per chunk = 8 k-steps of 8 ----
#pragma unroll
        for (int kk = 0; kk < 8; ++kk) {
            wmma::fragment<wmma::matrix_a, 16, 16, 8, wmma::precision::tf32, wmma::row_major> af[2];
#pragma unroll
            for (int i = 0; i < 2; ++i) {
                wmma::load_matrix_sync(af[i], AS + (wm * 32 + i * 16) * ALD + kk * 8, ALD);
#pragma unroll
                for (int t = 0; t < af[i].num_elements; ++t)
                    af[i].x[t] = wmma::__float_to_tf32(af[i].x[t]);
            }
#pragma unroll
            for (int j = 0; j < 4; ++j) {
                wmma::fragment<wmma::matrix_b, 16, 16, 8, wmma::precision::tf32, wmma::col_major> bf;
                wmma::load_matrix_sync(bf, BS + (wn * 64 + j * 16) * ALD + kk * 8, ALD);
#pragma unroll
                for (int t = 0; t < bf.num_elements; ++t)
                    bf.x[t] = wmma::__float_to_tf32(bf.x[t]);
#pragma unroll
                for (int i = 0; i < 2; ++i)
                    wmma::mma_sync(acc[i][j], af[i], bf, acc[i][j]);
            }
        }
        __syncthreads();   // done reading A/B before restage (or Ds overlay)
    }

    // ---- store D to smem overlay ----
#pragma unroll
    for (int i = 0; i < 2; ++i)
#pragma unroll
        for (int j = 0; j < 4; ++j)
            wmma::store_matrix_sync(Ds + (wm * 32 + i * 16) * DLD + wn * 64 + j * 16,
                                    acc[i][j], DLD, wmma::mem_row_major);
    __syncthreads();

    // ---- epilogue: hid + stats, gelu, @W2 partials ----
    {
        const int row  = tid >> 1;
        const int half = tid & 1;
        const int c0   = half * 64;
        const float* hrow = &hidc[(row >> 4) * 128];
        const float* drow = &Ds[row * DLD];
        float st[12];
#pragma unroll
        for (int j = 0; j < 12; ++j) st[j] = sStat[row * 12 + j];
        float lg0 = 0.f, lg1 = 0.f, lg2 = 0.f, lg3 = 0.f;
#pragma unroll 8
        for (int ci = 0; ci < 64; ++ci) {
            const int cc = c0 + ci;
            float a = drow[cc] + hrow[cc];
#pragma unroll
            for (int j = 0; j < 12; ++j) a = fmaf(st[j], sWst[j * NOUT + cc], a);
            a *= normcdff(a);                      // exact gelu
            const float4 w = *reinterpret_cast<const float4*>(&sW2[cc * 4]);
            lg0 = fmaf(a, w.x, lg0);
            lg1 = fmaf(a, w.y, lg1);
            lg2 = fmaf(a, w.z, lg2);
            lg3 = fmaf(a, w.w, lg3);
        }
        sLog[row * 8 + half * 4 + 0] = lg0;
        sLog[row * 8 + half * 4 + 1] = lg1;
        sLog[row * 8 + half * 4 + 2] = lg2;
        sLog[row * 8 + half * 4 + 3] = lg3;
    }
    __syncthreads();

    // ---- softmax / floor / renorm ----
    if (tid < 128) {
        const int m = m0 + tid;
        const int head = m & (HH - 1);
        float l0 = sLog[tid * 8 + 0] + sLog[tid * 8 + 4] + b2[0];
        float l1 = sLog[tid * 8 + 1] + sLog[tid * 8 + 5] + b2[1];
        float l2 = sLog[tid * 8 + 2] + sLog[tid * 8 + 6] + b2[2];
        float l3 = sLog[tid * 8 + 3] + sLog[tid * 8 + 7] + b2[3];
        const float t = fminf(fmaxf(temp[head], 0.2f), 10.f);
        const float inv_t = 1.f / t;
        const float mxl = fmaxf(fmaxf(l0, l1), fmaxf(l2, l3));
        const float e0 = expf((l0 - mxl) * inv_t);
        const float e1 = expf((l1 - mxl) * inv_t);
        const float e2 = expf((l2 - mxl) * inv_t);
        const float e3 = expf((l3 - mxl) * inv_t);
        const float inv = 1.f / (e0 + e1 + e2 + e3);
        float w0 = e0 * inv, w1 = e1 * inv, w2 = e2 * inv, w3 = e3 * inv;
        const float* ef = &eps_floor[head * 4];
        w0 = fmaxf(w0, fminf(fmaxf(ef[0], 1e-7f), 0.1f));
        w1 = fmaxf(w1, fminf(fmaxf(ef[1], 1e-7f), 0.1f));
        w2 = fmaxf(w2, fminf(fmaxf(ef[2], 1e-7f), 0.1f));
        w3 = fmaxf(w3, fminf(fmaxf(ef[3], 1e-7f), 0.1f));
        const float inv2 = 1.f / (w0 + w1 + w2 + w3);
        float4 o = {w0 * inv2, w1 * inv2, w2 * inv2, w3 * inv2};
        *reinterpret_cast<float4*>(&out[(size_t)m * 4]) = o;
    }
}

// ---------------------------------------------------------------------------
// Launch
// ---------------------------------------------------------------------------
extern "C" void kernel_launch(void* const* d_in, const int* in_sizes, int n_in,
                              void* d_out, int out_size) {
    const float* hidden = (const float*)d_in[0];
    const float* br0    = (const float*)d_in[1];
    const float* br1    = (const float*)d_in[2];
    const float* br2    = (const float*)d_in[3];
    const float* br3    = (const float*)d_in[4];
    const float* W1     = (const float*)d_in[5];
    const float* b1     = (const float*)d_in[6];
    const float* W2     = (const float*)d_in[7];
    const float* b2     = (const float*)d_in[8];
    const float* epsf   = (const float*)d_in[9];
    const float* temp   = (const float*)d_in[10];
    float* out = (float*)d_out;

    cudaFuncSetAttribute(hid_kernel, cudaFuncAttributeMaxDynamicSharedMemorySize,
                         HID_SMEM_BYTES);
    cudaFuncSetAttribute(main_wmma_kernel, cudaFuncAttributeMaxDynamicSharedMemorySize,
                         MAIN_SMEM_BYTES);

    hid_kernel<<<284, 256, HID_SMEM_BYTES>>>(hidden, W1, b1);
    main_wmma_kernel<<<NROWS / 128, 256, MAIN_SMEM_BYTES>>>(br0, br1, br2, br3,
                                                            W2, b2, epsf, temp, out);
}

// round 16
// speedup vs baseline: 2.7422x; 1.3120x over previous
#include <cuda_runtime.h>
#include <cuda_bf16.h>
#include <mma.h>
#include <math.h>
#include <math_constants.h>
#include <stdint.h>

using namespace nvcuda;

typedef unsigned long long ull;

// Problem constants
#define HH    16
#define DD    64
#define HIDN  1024
#define NROWS 65536         // B*L*H
#define NBL   4096          // B*L
#define NOUT  128           // 2*D

// __device__ scratch (allocation-free rule)
__device__ float g_hidp[4][NBL * NOUT];      // K-split partials of hidden@W1[:1024] (+b1 in part 0)
__device__ float g_wstat[12 * NOUT];         // fp32 column sums of W1 stat-block rows
__device__ __nv_bfloat16 g_Bhi[4][8192];     // branch-tail W1^T per chunk [n*64+k], hi part
__device__ __nv_bfloat16 g_Blo[4][8192];     // lo part

// ---------------------------------------------------------------------------
// helpers
// ---------------------------------------------------------------------------
__device__ __forceinline__ ull fma2(ull a, ull b, ull c) {
    ull d; asm("fma.rn.f32x2 %0, %1, %2, %3;" : "=l"(d) : "l"(a), "l"(b), "l"(c));
    return d;
}
__device__ __forceinline__ ull dup2(float x) {
    ull d; asm("mov.b64 %0, {%1, %1};" : "=l"(d) : "f"(x));
    return d;
}
__device__ __forceinline__ uint32_t cvt_bf16x2(float hi_elem, float lo_elem) {
    // bits [15:0] = bf16(lo_elem), [31:16] = bf16(hi_elem)
    uint32_t r;
    asm("cvt.rn.bf16x2.f32 %0, %1, %2;" : "=r"(r) : "f"(hi_elem), "f"(lo_elem));
    return r;
}
__device__ __forceinline__ void cp16(void* dst_smem, const void* src) {
    uint32_t d = (uint32_t)__cvta_generic_to_shared(dst_smem);
    asm volatile("cp.async.cg.shared.global [%0], [%1], 16;" :: "r"(d), "l"(src) : "memory");
}
#define CP_COMMIT() asm volatile("cp.async.commit_group;" ::: "memory")
#define CP_WAIT0()  asm volatile("cp.async.wait_group 0;" ::: "memory")

// ---------------------------------------------------------------------------
// hid + prep fused kernel (EXACT R9 winner).
// Blocks 0..255: FFMA2 hidden partial GEMM (rowgroup rg=bid>>2, K-split ks=bid&3)
// Blocks 256..271: branch-tail weight prep (bf16 hi/lo); Blocks 272..283: wstat
// ---------------------------------------------------------------------------
#define HID_SMEM_BYTES (12544 * 4)

__global__ __launch_bounds__(256)
void hid_kernel(const float* __restrict__ hidden,
                const float* __restrict__ W1,
                const float* __restrict__ b1) {
    if (blockIdx.x >= 256) {
        const int bid = blockIdx.x;
        if (bid < 272) {
            const int c = (bid - 256) >> 2, q = bid & 3;
            const int rowbase = 1792 + c * 64;
            const int e0 = q * 2048;
            for (int e = e0 + threadIdx.x; e < e0 + 2048; e += 256) {
                const int k = e >> 7, n = e & 127;
                const float x = W1[(size_t)(rowbase + k) * NOUT + n];
                const __nv_bfloat16 hi = __float2bfloat16(x);
                const __nv_bfloat16 lo = __float2bfloat16(x - __bfloat162float(hi));
                g_Bhi[c][n * 64 + k] = hi;
                g_Blo[c][n * 64 + k] = lo;
            }
        } else {
            const int j = bid - 272;
            const int o = threadIdx.x & 127;
            const int half = threadIdx.x >> 7;
            __shared__ float part[256];
            const float* base = W1 + (size_t)(HIDN + j * 64 + half * 32) * NOUT + o;
            float s = 0.f;
#pragma unroll
            for (int d = 0; d < 32; ++d) s += base[(size_t)d * NOUT];
            part[threadIdx.x] = s;
            __syncthreads();
            if (half == 0) g_wstat[j * NOUT + o] = part[o] + part[128 + o];
        }
        return;
    }

    extern __shared__ float sm[];
    float* Bs  = sm;           // [64][128]
    float* AsT = sm + 8192;    // [64][68]

    const int tid = threadIdx.x;
    const int rg  = blockIdx.x >> 2;
    const int ks  = blockIdx.x & 3;
    const int m0  = rg * 64;
    const int k0b = ks * 256;
    const int tx  = tid & 15, ty = tid >> 4;
    const int tx4 = tx * 4,  ty4 = ty * 4;

    ull acc[4][4] = {};

    for (int t = 0; t < 4; ++t) {
        const int k0 = k0b + t * 64;
        {
            int idx = tid;
#pragma unroll
            for (int i = 0; i < 16; ++i, idx += 256) {
                int r = idx >> 6, kk = idx & 63;
                AsT[kk * 68 + r] = hidden[(size_t)(m0 + r) * HIDN + k0 + kk];
            }
        }
        {
            int i4 = tid;
#pragma unroll
            for (int i = 0; i < 8; ++i, i4 += 256) {
                int kk = i4 >> 5, c4 = (i4 & 31) * 4;
                *reinterpret_cast<float4*>(&Bs[kk * 128 + c4]) =
                    *reinterpret_cast<const float4*>(&W1[(size_t)(k0 + kk) * NOUT + c4]);
            }
        }
        __syncthreads();

#pragma unroll 8
        for (int kk = 0; kk < 64; ++kk) {
            const float4 a4 = *reinterpret_cast<const float4*>(&AsT[kk * 68 + ty4]);
            const ulonglong2 bv0 = *reinterpret_cast<const ulonglong2*>(&Bs[kk * 128 + tx4]);
            const ulonglong2 bv1 = *reinterpret_cast<const ulonglong2*>(&Bs[kk * 128 + 64 + tx4]);
            ull ad[4] = {dup2(a4.x), dup2(a4.y), dup2(a4.z), dup2(a4.w)};
            ull bq[4] = {bv0.x, bv0.y, bv1.x, bv1.y};
#pragma unroll
            for (int i = 0; i < 4; ++i)
#pragma unroll
                for (int jj = 0; jj < 4; ++jj)
                    acc[i][jj] = fma2(ad[i], bq[jj], acc[i][jj]);
        }
        __syncthreads();
    }

    float* outp = g_hidp[ks];
    float4 bb0 = {0, 0, 0, 0}, bb1 = {0, 0, 0, 0};
    if (ks == 0) {
        bb0 = *reinterpret_cast<const float4*>(&b1[tx4]);
        bb1 = *reinterpret_cast<const float4*>(&b1[64 + tx4]);
    }
#pragma unroll
    for (int rr = 0; rr < 4; ++rr) {
        const int r = ty4 + rr;
        float2 p0 = *reinterpret_cast<float2*>(&acc[rr][0]);
        float2 p1 = *reinterpret_cast<float2*>(&acc[rr][1]);
        float2 p2 = *reinterpret_cast<float2*>(&acc[rr][2]);
        float2 p3 = *reinterpret_cast<float2*>(&acc[rr][3]);
        float4 v0 = {p0.x + bb0.x, p0.y + bb0.y, p1.x + bb0.z, p1.y + bb0.w};
        float4 v1 = {p2.x + bb1.x, p2.y + bb1.y, p3.x + bb1.z, p3.y + bb1.w};
        *reinterpret_cast<float4*>(&outp[(size_t)(m0 + r) * NOUT + tx4]) = v0;
        *reinterpret_cast<float4*>(&outp[(size_t)(m0 + r) * NOUT + 64 + tx4]) = v1;
    }
}

// ---------------------------------------------------------------------------
// main: wmma bf16 2-combo GEMM: D = Ahi @ (Bhi + Blo).
// A rounded to bf16 (single buffer, single cvt); B keeps hi/lo split so the
// weight side stays ~fp32-precise. R9 shell otherwise: M-tile 128, N=128,
// K=256 (4 chunks), 8 warps 4(M)x2(N), cp.async B, __launch_bounds__(256,2).
//
// smem (bytes):
//   AH 0      (128x72 bf16 = 18432)
//   BH 18432  | BL 36864  (.. 55296)
//   Ds[128][136] f32 overlay = 69632 B -> WST must start at >= 69632
//   WST 69632 | SST 75776 | W2 81920 | HIDC 83968 | SLOG 88064
//   total 92160 -> 2 CTAs/SM
// ---------------------------------------------------------------------------
#define OFF_AH   0
#define OFF_BH   18432
#define OFF_BL   36864
#define OFF_WST  69632
#define OFF_SST  75776
#define OFF_W2   81920
#define OFF_HIDC 83968
#define OFF_SLOG 88064
#define MAIN_SMEM_BYTES 92160

#define ALD 72     // A/B smem leading dim (bf16 elements)
#define DLD 136    // D smem leading dim (floats)

__global__ __launch_bounds__(256, 2)
void main_wmma_kernel(const float* __restrict__ br0, const float* __restrict__ br1,
                      const float* __restrict__ br2, const float* __restrict__ br3,
                      const float* __restrict__ W2,  const float* __restrict__ b2,
                      const float* __restrict__ eps_floor,
                      const float* __restrict__ temp, float* __restrict__ out) {
    extern __shared__ char smc[];
    __nv_bfloat16* AH = reinterpret_cast<__nv_bfloat16*>(smc + OFF_AH);
    __nv_bfloat16* BH = reinterpret_cast<__nv_bfloat16*>(smc + OFF_BH);
    __nv_bfloat16* BL = reinterpret_cast<__nv_bfloat16*>(smc + OFF_BL);
    float* Ds    = reinterpret_cast<float*>(smc);             // epilogue overlay
    float* sWst  = reinterpret_cast<float*>(smc + OFF_WST);
    float* sStat = reinterpret_cast<float*>(smc + OFF_SST);
    float* sW2   = reinterpret_cast<float*>(smc + OFF_W2);
    float* hidc  = reinterpret_cast<float*>(smc + OFF_HIDC);
    float* sLog  = reinterpret_cast<float*>(smc + OFF_SLOG);

    const int tid = threadIdx.x;
    const int wid = tid >> 5;
    const int m0  = blockIdx.x * 128;
    const int wm  = wid & 3, wn = wid >> 2;

    // Prologue one-time loads (covered by chunk-0 __syncthreads)
    for (int i = tid; i < 1024; i += 256) {
        const size_t g = (size_t)(blockIdx.x * 8) * NOUT + i;
        hidc[i] = (g_hidp[0][g] + g_hidp[1][g]) + (g_hidp[2][g] + g_hidp[3][g]);
    }
    for (int i = tid; i < 512; i += 256)       sW2[i]  = W2[i];
    for (int i = tid; i < 12 * NOUT; i += 256) sWst[i] = g_wstat[i];

    wmma::fragment<wmma::accumulator, 16, 16, 16, float> acc[2][4];
#pragma unroll
    for (int i = 0; i < 2; ++i)
#pragma unroll
        for (int j = 0; j < 4; ++j) wmma::fill_fragment(acc[i][j], 0.0f);

    const int arow  = tid >> 1;
    const int ahalf = tid & 1;
    const int kbase = ahalf * 32;

#pragma unroll 1
    for (int p = 0; p < 4; ++p) {
        const float* brp = (p == 0) ? br0 : (p == 1) ? br1 : (p == 2) ? br2 : br3;

        // ---- issue async B copies first (overlap with A convert below) ----
        {
            const int n = tid >> 1;
            const int kb = ahalf * 32;
#pragma unroll
            for (int q = 0; q < 4; ++q) {
                cp16(&BH[n * ALD + kb + q * 8], &g_Bhi[p][n * 64 + kb + q * 8]);
                cp16(&BL[n * ALD + kb + q * 8], &g_Blo[p][n * 64 + kb + q * 8]);
            }
            CP_COMMIT();
        }

        // ---- stage A (single bf16 round) + stats ----
        {
            const float* src = brp + (size_t)(m0 + arow) * DD + kbase;
            float s = 0.f, sq = 0.f, mx = -CUDART_INF_F;
#pragma unroll
            for (int j = 0; j < 8; ++j) {
                const float4 v = *reinterpret_cast<const float4*>(src + j * 4);
                s += (v.x + v.y) + (v.z + v.w);
                sq = fmaf(v.x, v.x, sq); sq = fmaf(v.y, v.y, sq);
                sq = fmaf(v.z, v.z, sq); sq = fmaf(v.w, v.w, sq);
                mx = fmaxf(mx, fmaxf(fmaxf(v.x, v.y), fmaxf(v.z, v.w)));
                const uint32_t h0 = cvt_bf16x2(v.y, v.x);
                const uint32_t h1 = cvt_bf16x2(v.w, v.z);
                uint2 hv = {h0, h1};
                *reinterpret_cast<uint2*>(&AH[arow * ALD + kbase + j * 4]) = hv;
            }
            s  += __shfl_xor_sync(0xffffffffu, s, 1);
            sq += __shfl_xor_sync(0xffffffffu, sq, 1);
            mx  = fmaxf(mx, __shfl_xor_sync(0xffffffffu, mx, 1));
            if (ahalf == 0) {
                sStat[arow * 12 + p * 3 + 0] = s * (1.f / 64.f);
                sStat[arow * 12 + p * 3 + 1] = sqrtf(fmaxf(sq * (1.f / 64.f), 1e-8f));
                sStat[arow * 12 + p * 3 + 2] = mx;
            }
        }

        CP_WAIT0();
        __syncthreads();

        // ---- HMMA: Ahi@Bhi + Ahi@Blo (64 MMAs/warp/chunk) ----
#pragma unroll
        for (int kk = 0; kk < 4; ++kk) {
            wmma::fragment<wmma::matrix_a, 16, 16, 16, __nv_bfloat16, wmma::row_major> ahi[2];
#pragma unroll
            for (int i = 0; i < 2; ++i)
                wmma::load_matrix_sync(ahi[i], AH + (wm * 32 + i * 16) * ALD + kk * 16, ALD);
#pragma unroll
            for (int j = 0; j < 4; ++j) {
                wmma::fragment<wmma::matrix_b, 16, 16, 16, __nv_bfloat16, wmma::col_major> bhi, blo;
                const int bo = (wn * 64 + j * 16) * ALD + kk * 16;
                wmma::load_matrix_sync(bhi, BH + bo, ALD);
                wmma::load_matrix_sync(blo, BL + bo, ALD);
#pragma unroll
                for (int i = 0; i < 2; ++i) {
                    wmma::mma_sync(acc[i][j], ahi[i], bhi, acc[i][j]);
                    wmma::mma_sync(acc[i][j], ahi[i], blo, acc[i][j]);
                }
            }
        }
        __syncthreads();   // done reading A/B before restage (or Ds overlay)
    }

    // ---- store D to smem overlay ----
#pragma unroll
    for (int i = 0; i < 2; ++i)
#pragma unroll
        for (int j = 0; j < 4; ++j)
            wmma::store_matrix_sync(Ds + (wm * 32 + i * 16) * DLD + wn * 64 + j * 16,
                                    acc[i][j], DLD, wmma::mem_row_major);
    __syncthreads();

    // ---- epilogue: hid + stats, gelu, @W2 partials ----
    {
        const int row  = tid >> 1;
        const int half = tid & 1;
        const int c0   = half * 64;
        const float* hrow = &hidc[(row >> 4) * 128];
        const float* drow = &Ds[row * DLD];
        float st[12];
#pragma unroll
        for (int j = 0; j < 12; ++j) st[j] = sStat[row * 12 + j];
        float lg0 = 0.f, lg1 = 0.f, lg2 = 0.f, lg3 = 0.f;
#pragma unroll 8
        for (int ci = 0; ci < 64; ++ci) {
            const int cc = c0 + ci;
            float a = drow[cc] + hrow[cc];
#pragma unroll
            for (int j = 0; j < 12; ++j) a = fmaf(st[j], sWst[j * NOUT + cc], a);
            a *= normcdff(a);                      // exact gelu
            const float4 w = *reinterpret_cast<const float4*>(&sW2[cc * 4]);
            lg0 = fmaf(a, w.x, lg0);
            lg1 = fmaf(a, w.y, lg1);
            lg2 = fmaf(a, w.z, lg2);
            lg3 = fmaf(a, w.w, lg3);
        }
        sLog[row * 8 + half * 4 + 0] = lg0;
        sLog[row * 8 + half * 4 + 1] = lg1;
        sLog[row * 8 + half * 4 + 2] = lg2;
        sLog[row * 8 + half * 4 + 3] = lg3;
    }
    __syncthreads();

    // ---- softmax / floor / renorm ----
    if (tid < 128) {
        const int m = m0 + tid;
        const int head = m & (HH - 1);
        float l0 = sLog[tid * 8 + 0] + sLog[tid * 8 + 4] + b2[0];
        float l1 = sLog[tid * 8 + 1] + sLog[tid * 8 + 5] + b2[1];
        float l2 = sLog[tid * 8 + 2] + sLog[tid * 8 + 6] + b2[2];
        float l3 = sLog[tid * 8 + 3] + sLog[tid * 8 + 7] + b2[3];
        const float t = fminf(fmaxf(temp[head], 0.2f), 10.f);
        const float inv_t = 1.f / t;
        const float mxl = fmaxf(fmaxf(l0, l1), fmaxf(l2, l3));
        const float e0 = expf((l0 - mxl) * inv_t);
        const float e1 = expf((l1 - mxl) * inv_t);
        const float e2 = expf((l2 - mxl) * inv_t);
        const float e3 = expf((l3 - mxl) * inv_t);
        const float inv = 1.f / (e0 + e1 + e2 + e3);
        float w0 = e0 * inv, w1 = e1 * inv, w2 = e2 * inv, w3 = e3 * inv;
        const float* ef = &eps_floor[head * 4];
        w0 = fmaxf(w0, fminf(fmaxf(ef[0], 1e-7f), 0.1f));
        w1 = fmaxf(w1, fminf(fmaxf(ef[1], 1e-7f), 0.1f));
        w2 = fmaxf(w2, fminf(fmaxf(ef[2], 1e-7f), 0.1f));
        w3 = fmaxf(w3, fminf(fmaxf(ef[3], 1e-7f), 0.1f));
        const float inv2 = 1.f / (w0 + w1 + w2 + w3);
        float4 o = {w0 * inv2, w1 * inv2, w2 * inv2, w3 * inv2};
        *reinterpret_cast<float4*>(&out[(size_t)m * 4]) = o;
    }
}

// ---------------------------------------------------------------------------
// Launch
// ---------------------------------------------------------------------------
extern "C" void kernel_launch(void* const* d_in, const int* in_sizes, int n_in,
                              void* d_out, int out_size) {
    const float* hidden = (const float*)d_in[0];
    const float* br0    = (const float*)d_in[1];
    const float* br1    = (const float*)d_in[2];
    const float* br2    = (const float*)d_in[3];
    const float* br3    = (const float*)d_in[4];
    const float* W1     = (const float*)d_in[5];
    const float* b1     = (const float*)d_in[6];
    const float* W2     = (const float*)d_in[7];
    const float* b2     = (const float*)d_in[8];
    const float* epsf   = (const float*)d_in[9];
    const float* temp   = (const float*)d_in[10];
    float* out = (float*)d_out;

    cudaFuncSetAttribute(hid_kernel, cudaFuncAttributeMaxDynamicSharedMemorySize,
                         HID_SMEM_BYTES);
    cudaFuncSetAttribute(main_wmma_kernel, cudaFuncAttributeMaxDynamicSharedMemorySize,
                         MAIN_SMEM_BYTES);

    hid_kernel<<<284, 256, HID_SMEM_BYTES>>>(hidden, W1, b1);
    main_wmma_kernel<<<NROWS / 128, 256, MAIN_SMEM_BYTES>>>(br0, br1, br2, br3,
                                                            W2, b2, epsf, temp, out);
}